// round 16
// baseline (speedup 1.0000x reference)
#include <cuda_runtime.h>

// Problem constants (fixed by the reference setup)
#define S1   32      // patches per image side (256/8)
#define LTOK 320     // tokens per patch problem: N * ip * ip = 5*64
#define NQUAD (LTOK/4)
#define NTHR 160     // threads per block; TWO queries per thread (t, t+160)
#define NN   5
#define IP   8
#define HH   256
#define MID  2       // N//2
#define NBLK (S1*S1) // 1024: one CTA per patch

__device__ float    g_mid_acc;
__device__ float    g_all_acc;
__device__ float    g_rec_acc;
__device__ unsigned g_done;

// ---------- f32x2 packed-math helpers (Blackwell FFMA2 path, PTX-only) ----------
typedef unsigned long long ull;

__device__ __forceinline__ ull pack2(float lo, float hi) {
    ull r;
    asm("mov.b64 %0, {%1, %2};" : "=l"(r) : "f"(lo), "f"(hi));
    return r;
}
__device__ __forceinline__ void unpack2(ull v, float& lo, float& hi) {
    asm("mov.b64 {%0, %1}, %2;" : "=f"(lo), "=f"(hi) : "l"(v));
}
__device__ __forceinline__ ull fma2(ull a, ull b, ull c) {
    ull d;
    asm("fma.rn.f32x2 %0, %1, %2, %3;" : "=l"(d) : "l"(a), "l"(b), "l"(c));
    return d;
}
__device__ __forceinline__ ull add2(ull a, ull b) {
    ull d;
    asm("add.rn.f32x2 %0, %1, %2;" : "=l"(d) : "l"(a), "l"(b));
    return d;
}
__device__ __forceinline__ float ex2a(float x) {
    float y;
    asm("ex2.approx.ftz.f32 %0, %1;" : "=f"(y) : "f"(x));
    return y;
}

__global__ void __launch_bounds__(NTHR) attn_loss_kernel(
    const float* __restrict__ inp,       // (1,5,3,256,256)
    const float* __restrict__ outp,      // (1,5,3,256,256)
    const float* __restrict__ Wq,        // (3,3)
    const float* __restrict__ Wk,        // (3,3)
    const float* __restrict__ bq,        // (3,)
    const float* __restrict__ bk,        // (3,)
    const float* __restrict__ bv,        // (3,)
    const float* __restrict__ loss_diff, // scalar
    const int*   __restrict__ step,      // scalar
    const int*   __restrict__ max_steps, // scalar
    float* __restrict__ out)             // out[0]=loss, out+1 = rec_image (3*256*256)
{
    // Quad-packed raw-token SMEM: only x stored; k,v derived algebraically.
    __shared__ __align__(16) float X0_f[LTOK];
    __shared__ __align__(16) float X1_f[LTOK];
    __shared__ __align__(16) float X2_f[LTOK];
    __shared__ float  outS[LTOK][3];     // all 320 query outputs of this patch
    __shared__ float  wp[27];            // Wq[0:9] Wk[9:18] bq[18:21] bk[21:24] bv[24:27]
    __shared__ float  red[3];            // block partials: mid, all, rec

    const int t  = threadIdx.x;
    const int r  = blockIdx.x;           // patch index
    const int r1 = r >> 5;               // patch row
    const int r2 = r & 31;               // patch col

    if (t < 9)       wp[t] = Wq[t];
    else if (t < 18) wp[t] = Wk[t - 9];
    else if (t < 21) wp[t] = bq[t - 18];
    else if (t < 24) wp[t] = bk[t - 21];
    else if (t < 27) wp[t] = bv[t - 24];
    if (t == 0) { red[0] = 0.f; red[1] = 0.f; red[2] = 0.f; }
    __syncthreads();

    // ---- stage raw tokens x AND build the two queries this thread owns ----
    // score(token) = (Wk^T q).x + q.bk  in log2 domain (q pre-scaled by
    // 1/sqrt(3)*log2e); v = x + bv folded into the epilogue.
    float qk0[2], qk1[2], qk2[2], qb[2];
#pragma unroll
    for (int i = 0; i < 2; i++) {
        const int tt = t + i * NTHR;     // token id 0..319 (also this thread's query i)
        const int n  = tt >> 6;
        const int pp = tt & 63;
        const int h  = r1 * IP + (pp >> 3);
        const int w  = r2 * IP + (pp & 7);
        const int base = ((n * 3) * HH + h) * HH + w;
        const float x0 = inp[base];
        const float x1 = inp[base + HH * HH];
        const float x2 = inp[base + 2 * HH * HH];
        X0_f[tt] = x0;
        X1_f[tt] = x1;
        X2_f[tt] = x2;

        const float qs = 0.5773502691896258f * 1.4426950408889634f;
        const float q0 = (wp[0] * x0 + wp[1] * x1 + wp[2] * x2 + wp[18]) * qs;
        const float q1 = (wp[3] * x0 + wp[4] * x1 + wp[5] * x2 + wp[19]) * qs;
        const float q2 = (wp[6] * x0 + wp[7] * x1 + wp[8] * x2 + wp[20]) * qs;
        qk0[i] = q0 * wp[9]  + q1 * wp[12] + q2 * wp[15];
        qk1[i] = q0 * wp[10] + q1 * wp[13] + q2 * wp[16];
        qk2[i] = q0 * wp[11] + q1 * wp[14] + q2 * wp[17];
        qb[i]  = q0 * wp[21] + q1 * wp[22] + q2 * wp[23];
    }
    __syncthreads();

    // ---- streaming softmax-attention: 2 queries x 4 tokens per iteration ----
    const ull k0a = pack2(qk0[0], qk0[0]), k0b = pack2(qk0[1], qk0[1]);
    const ull k1a = pack2(qk1[0], qk1[0]), k1b = pack2(qk1[1], qk1[1]);
    const ull k2a = pack2(qk2[0], qk2[0]), k2b = pack2(qk2[1], qk2[1]);
    const ull bba = pack2(qb[0],  qb[0]),  bbb = pack2(qb[1],  qb[1]);

    ull seA = 0ull, a0A = 0ull, a1A = 0ull, a2A = 0ull;   // query t
    ull seB = 0ull, a0B = 0ull, a1B = 0ull, a2B = 0ull;   // query t+160

    const ulonglong2* __restrict__ P0 = (const ulonglong2*)X0_f;
    const ulonglong2* __restrict__ P1 = (const ulonglong2*)X1_f;
    const ulonglong2* __restrict__ P2 = (const ulonglong2*)X2_f;

#pragma unroll 4
    for (int m = 0; m < NQUAD; m++) {
        const ulonglong2 p0 = P0[m];     // x0 pairs (lo, hi)
        const ulonglong2 p1 = P1[m];     // x1 pairs
        const ulonglong2 p2 = P2[m];     // x2 pairs

        // query A scores (4 tokens)
        ull sa = fma2(k0a, p0.x, bba);
        ull sb = fma2(k0a, p0.y, bba);
        sa = fma2(k1a, p1.x, sa);
        sb = fma2(k1a, p1.y, sb);
        sa = fma2(k2a, p2.x, sa);
        sb = fma2(k2a, p2.y, sb);
        // query B scores (4 tokens)
        ull sc = fma2(k0b, p0.x, bbb);
        ull sd = fma2(k0b, p0.y, bbb);
        sc = fma2(k1b, p1.x, sc);
        sd = fma2(k1b, p1.y, sd);
        sc = fma2(k2b, p2.x, sc);
        sd = fma2(k2b, p2.y, sd);

        float c0, c1, c2, c3, d0, d1, d2, d3;
        unpack2(sa, c0, c1);
        unpack2(sb, c2, c3);
        unpack2(sc, d0, d1);
        unpack2(sd, d2, d3);
        const ull eaA = pack2(ex2a(c0), ex2a(c1));
        const ull ebA = pack2(ex2a(c2), ex2a(c3));
        const ull eaB = pack2(ex2a(d0), ex2a(d1));
        const ull ebB = pack2(ex2a(d2), ex2a(d3));

        seA = add2(seA, eaA);
        seA = add2(seA, ebA);
        a0A = fma2(eaA, p0.x, a0A);
        a0A = fma2(ebA, p0.y, a0A);
        a1A = fma2(eaA, p1.x, a1A);
        a1A = fma2(ebA, p1.y, a1A);
        a2A = fma2(eaA, p2.x, a2A);
        a2A = fma2(ebA, p2.y, a2A);

        seB = add2(seB, eaB);
        seB = add2(seB, ebB);
        a0B = fma2(eaB, p0.x, a0B);
        a0B = fma2(ebB, p0.y, a0B);
        a1B = fma2(eaB, p1.x, a1B);
        a1B = fma2(ebB, p1.y, a1B);
        a2B = fma2(eaB, p2.x, a2B);
        a2B = fma2(ebB, p2.y, a2B);
    }

    {
        float sA, sB, u0, u1, v0, v1, w0, w1;
        unpack2(seA, sA, sB);
        unpack2(a0A, u0, u1);
        unpack2(a1A, v0, v1);
        unpack2(a2A, w0, w1);
        const float inv = 1.0f / (sA + sB);
        // v = x + bv  =>  out = (sum e*x)/sum e + bv
        outS[t][0] = (u0 + u1) * inv + wp[24];
        outS[t][1] = (v0 + v1) * inv + wp[25];
        outS[t][2] = (w0 + w1) * inv + wp[26];
        unpack2(seB, sA, sB);
        unpack2(a0B, u0, u1);
        unpack2(a1B, v0, v1);
        unpack2(a2B, w0, w1);
        const float inv2 = 1.0f / (sA + sB);
        outS[t + NTHR][0] = (u0 + u1) * inv2 + wp[24];
        outS[t + NTHR][1] = (v0 + v1) * inv2 + wp[25];
        outS[t + NTHR][2] = (w0 + w1) * inv2 + wp[26];
    }
    __syncthreads();

    // ---- losses (full patch: 960 elements) ----
    float lm = 0.f, la = 0.f, lr = 0.f;

    // all_loss / mid_loss: 960 elements (n,c,ph,pw), 6 per thread
#pragma unroll
    for (int i = 0; i < 6; i++) {
        const int e   = t + i * NTHR;
        const int n2  = e / 192;
        const int rem = e - n2 * 192;
        const int c   = rem >> 6;
        const int pp2 = rem & 63;
        const int h2  = r1 * IP + (pp2 >> 3);
        const int w2  = r2 * IP + (pp2 & 7);
        const float nin  = outp[((n2 * 3 + c) * HH + h2) * HH + w2];
        const float ninm = outp[((MID * 3 + c) * HH + h2) * HH + w2];
        const float al   = outS[n2 * 64 + pp2][c];
        const float da = nin - al;
        const float dm = ninm - al;
        la += da * da;
        lm += dm * dm;
    }

    // rec (mean over N) + rec_image write + rec_loss partial: 192 elements
    float* __restrict__ rec_out = out + 1;
#pragma unroll
    for (int i = 0; i < 2; i++) {
        const int e = t + i * NTHR;
        if (e < 192) {
            const int c   = e >> 6;
            const int pp2 = e & 63;
            const int h2  = r1 * IP + (pp2 >> 3);
            const int w2  = r2 * IP + (pp2 & 7);
            const float rec = 0.2f * (outS[pp2][c] + outS[64 + pp2][c] + outS[128 + pp2][c]
                                      + outS[192 + pp2][c] + outS[256 + pp2][c]);
            rec_out[(c * HH + h2) * HH + w2] = rec;
            const float om = outp[((MID * 3 + c) * HH + h2) * HH + w2];
            const float d  = om - rec;
            lr += d * d;
        }
    }

    // warp reduce then block reduce
#pragma unroll
    for (int o = 16; o > 0; o >>= 1) {
        lm += __shfl_down_sync(0xffffffffu, lm, o);
        la += __shfl_down_sync(0xffffffffu, la, o);
        lr += __shfl_down_sync(0xffffffffu, lr, o);
    }
    if ((t & 31) == 0) {
        atomicAdd(&red[0], lm);
        atomicAdd(&red[1], la);
        atomicAdd(&red[2], lr);
    }
    __syncthreads();

    if (t == 0) {
        atomicAdd(&g_mid_acc, red[0] * (1.0f / 960.0f));
        atomicAdd(&g_all_acc, red[1] * (1.0f / 960.0f));
        atomicAdd(&g_rec_acc, red[2]);
        __threadfence();
        const unsigned old = atomicAdd(&g_done, 1u);
        if (old == NBLK - 1) {
            // Last CTA: all accumulators visible. Finalize the loss.
            const float mid = atomicAdd(&g_mid_acc, 0.0f);
            const float all = atomicAdd(&g_all_acc, 0.0f);
            const float rcc = atomicAdd(&g_rec_acc, 0.0f);
            const float frac = 1.0f - (float)step[0] / (float)max_steps[0];
            const float f2 = frac * frac;
            const float f4 = f2 * f2;
            const float f8 = f4 * f4;
            const float coeff = loss_diff[0] * (f8 * f2);   // frac^10
            out[0] = mid + coeff * all + rcc * (1.0f / 196608.0f);
            // Reset globals for the next graph replay (zero-init covers call 1).
            g_mid_acc = 0.0f;
            g_all_acc = 0.0f;
            g_rec_acc = 0.0f;
            __threadfence();
            g_done = 0u;
        }
    }
}

extern "C" void kernel_launch(void* const* d_in, const int* in_sizes, int n_in,
                              void* d_out, int out_size)
{
    const float* inp  = (const float*)d_in[0];
    const float* outp = (const float*)d_in[1];
    const float* Wq   = (const float*)d_in[2];
    const float* Wk   = (const float*)d_in[3];
    const float* bq   = (const float*)d_in[4];
    const float* bk   = (const float*)d_in[5];
    const float* bv   = (const float*)d_in[6];
    const float* ld   = (const float*)d_in[7];
    const int*   st   = (const int*)d_in[8];
    const int*   ms   = (const int*)d_in[9];
    float* out = (float*)d_out;

    attn_loss_kernel<<<NBLK, NTHR>>>(inp, outp, Wq, Wk, bq, bk, bv, ld, st, ms, out);
}

// round 17
// speedup vs baseline: 1.0065x; 1.0065x over previous
#include <cuda_runtime.h>

// Problem constants (fixed by the reference setup)
#define S1   32      // patches per image side (256/8)
#define LTOK 320     // tokens per patch problem: N * ip * ip = 5*64
#define NQUAD (LTOK/4)
#define NTHR 160     // threads per block; TWO queries per thread (t, t+160)
#define NN   5
#define IP   8
#define HH   256
#define MID  2       // N//2
#define NBLK (S1*S1) // 1024: one CTA per patch

__device__ float    g_mid_acc;
__device__ float    g_all_acc;
__device__ float    g_rec_acc;
__device__ unsigned g_done;

// ---------- f32x2 packed-math helpers (Blackwell FFMA2 path, PTX-only) ----------
typedef unsigned long long ull;

__device__ __forceinline__ ull pack2(float lo, float hi) {
    ull r;
    asm("mov.b64 %0, {%1, %2};" : "=l"(r) : "f"(lo), "f"(hi));
    return r;
}
__device__ __forceinline__ void unpack2(ull v, float& lo, float& hi) {
    asm("mov.b64 {%0, %1}, %2;" : "=f"(lo), "=f"(hi) : "l"(v));
}
__device__ __forceinline__ ull fma2(ull a, ull b, ull c) {
    ull d;
    asm("fma.rn.f32x2 %0, %1, %2, %3;" : "=l"(d) : "l"(a), "l"(b), "l"(c));
    return d;
}
__device__ __forceinline__ ull add2(ull a, ull b) {
    ull d;
    asm("add.rn.f32x2 %0, %1, %2;" : "=l"(d) : "l"(a), "l"(b));
    return d;
}
__device__ __forceinline__ float ex2a(float x) {
    float y;
    asm("ex2.approx.ftz.f32 %0, %1;" : "=f"(y) : "f"(x));
    return y;
}

__global__ void __launch_bounds__(NTHR) attn_loss_kernel(
    const float* __restrict__ inp,       // (1,5,3,256,256)
    const float* __restrict__ outp,      // (1,5,3,256,256)
    const float* __restrict__ Wq,        // (3,3)
    const float* __restrict__ Wk,        // (3,3)
    const float* __restrict__ bq,        // (3,)
    const float* __restrict__ bk,        // (3,)
    const float* __restrict__ bv,        // (3,)
    const float* __restrict__ loss_diff, // scalar
    const int*   __restrict__ step,      // scalar
    const int*   __restrict__ max_steps, // scalar
    float* __restrict__ out)             // out[0]=loss, out+1 = rec_image (3*256*256)
{
    // Quad-packed raw-token SMEM: only x stored; k,v derived algebraically.
    __shared__ __align__(16) float X0_f[LTOK];
    __shared__ __align__(16) float X1_f[LTOK];
    __shared__ __align__(16) float X2_f[LTOK];
    __shared__ float  outS[LTOK][3];     // all 320 query outputs of this patch
    __shared__ float  wp[27];            // Wq[0:9] Wk[9:18] bq[18:21] bk[21:24] bv[24:27]
    __shared__ float  red[3];            // block partials: mid, all, rec

    const int t  = threadIdx.x;
    const int r  = blockIdx.x;           // patch index
    const int r1 = r >> 5;               // patch row
    const int r2 = r & 31;               // patch col

    if (t < 9)       wp[t] = Wq[t];
    else if (t < 18) wp[t] = Wk[t - 9];
    else if (t < 21) wp[t] = bq[t - 18];
    else if (t < 24) wp[t] = bk[t - 21];
    else if (t < 27) wp[t] = bv[t - 24];
    if (t == 0) { red[0] = 0.f; red[1] = 0.f; red[2] = 0.f; }
    __syncthreads();

    // ---- stage raw tokens x AND build the two queries this thread owns ----
    // score(token) = (Wk^T q).x + q.bk  in log2 domain (q pre-scaled by
    // 1/sqrt(3)*log2e); v = x + bv folded into the epilogue.
    float qk0[2], qk1[2], qk2[2], qb[2];
#pragma unroll
    for (int i = 0; i < 2; i++) {
        const int tt = t + i * NTHR;     // token id 0..319 (also this thread's query i)
        const int n  = tt >> 6;
        const int pp = tt & 63;
        const int h  = r1 * IP + (pp >> 3);
        const int w  = r2 * IP + (pp & 7);
        const int base = ((n * 3) * HH + h) * HH + w;
        const float x0 = inp[base];
        const float x1 = inp[base + HH * HH];
        const float x2 = inp[base + 2 * HH * HH];
        X0_f[tt] = x0;
        X1_f[tt] = x1;
        X2_f[tt] = x2;

        const float qs = 0.5773502691896258f * 1.4426950408889634f;
        const float q0 = (wp[0] * x0 + wp[1] * x1 + wp[2] * x2 + wp[18]) * qs;
        const float q1 = (wp[3] * x0 + wp[4] * x1 + wp[5] * x2 + wp[19]) * qs;
        const float q2 = (wp[6] * x0 + wp[7] * x1 + wp[8] * x2 + wp[20]) * qs;
        qk0[i] = q0 * wp[9]  + q1 * wp[12] + q2 * wp[15];
        qk1[i] = q0 * wp[10] + q1 * wp[13] + q2 * wp[16];
        qk2[i] = q0 * wp[11] + q1 * wp[14] + q2 * wp[17];
        qb[i]  = q0 * wp[21] + q1 * wp[22] + q2 * wp[23];
    }
    __syncthreads();

    // ---- streaming softmax-attention: 2 queries x 4 tokens per iteration ----
    const ull k0a = pack2(qk0[0], qk0[0]), k0b = pack2(qk0[1], qk0[1]);
    const ull k1a = pack2(qk1[0], qk1[0]), k1b = pack2(qk1[1], qk1[1]);
    const ull k2a = pack2(qk2[0], qk2[0]), k2b = pack2(qk2[1], qk2[1]);
    const ull bba = pack2(qb[0],  qb[0]),  bbb = pack2(qb[1],  qb[1]);

    ull seA = 0ull, a0A = 0ull, a1A = 0ull, a2A = 0ull;   // query t
    ull seB = 0ull, a0B = 0ull, a1B = 0ull, a2B = 0ull;   // query t+160

    const ulonglong2* __restrict__ P0 = (const ulonglong2*)X0_f;
    const ulonglong2* __restrict__ P1 = (const ulonglong2*)X1_f;
    const ulonglong2* __restrict__ P2 = (const ulonglong2*)X2_f;

#pragma unroll 4
    for (int m = 0; m < NQUAD; m++) {
        const ulonglong2 p0 = P0[m];     // x0 pairs (lo, hi)
        const ulonglong2 p1 = P1[m];     // x1 pairs
        const ulonglong2 p2 = P2[m];     // x2 pairs

        // query A scores (4 tokens)
        ull sa = fma2(k0a, p0.x, bba);
        ull sb = fma2(k0a, p0.y, bba);
        sa = fma2(k1a, p1.x, sa);
        sb = fma2(k1a, p1.y, sb);
        sa = fma2(k2a, p2.x, sa);
        sb = fma2(k2a, p2.y, sb);
        // query B scores (4 tokens)
        ull sc = fma2(k0b, p0.x, bbb);
        ull sd = fma2(k0b, p0.y, bbb);
        sc = fma2(k1b, p1.x, sc);
        sd = fma2(k1b, p1.y, sd);
        sc = fma2(k2b, p2.x, sc);
        sd = fma2(k2b, p2.y, sd);

        float c0, c1, c2, c3, d0, d1, d2, d3;
        unpack2(sa, c0, c1);
        unpack2(sb, c2, c3);
        unpack2(sc, d0, d1);
        unpack2(sd, d2, d3);
        const ull eaA = pack2(ex2a(c0), ex2a(c1));
        const ull ebA = pack2(ex2a(c2), ex2a(c3));
        const ull eaB = pack2(ex2a(d0), ex2a(d1));
        const ull ebB = pack2(ex2a(d2), ex2a(d3));

        seA = add2(seA, eaA);
        seA = add2(seA, ebA);
        a0A = fma2(eaA, p0.x, a0A);
        a0A = fma2(ebA, p0.y, a0A);
        a1A = fma2(eaA, p1.x, a1A);
        a1A = fma2(ebA, p1.y, a1A);
        a2A = fma2(eaA, p2.x, a2A);
        a2A = fma2(ebA, p2.y, a2A);

        seB = add2(seB, eaB);
        seB = add2(seB, ebB);
        a0B = fma2(eaB, p0.x, a0B);
        a0B = fma2(ebB, p0.y, a0B);
        a1B = fma2(eaB, p1.x, a1B);
        a1B = fma2(ebB, p1.y, a1B);
        a2B = fma2(eaB, p2.x, a2B);
        a2B = fma2(ebB, p2.y, a2B);
    }

    {
        float sA, sB, u0, u1, v0, v1, w0, w1;
        unpack2(seA, sA, sB);
        unpack2(a0A, u0, u1);
        unpack2(a1A, v0, v1);
        unpack2(a2A, w0, w1);
        const float inv = 1.0f / (sA + sB);
        // v = x + bv  =>  out = (sum e*x)/sum e + bv
        outS[t][0] = (u0 + u1) * inv + wp[24];
        outS[t][1] = (v0 + v1) * inv + wp[25];
        outS[t][2] = (w0 + w1) * inv + wp[26];
        unpack2(seB, sA, sB);
        unpack2(a0B, u0, u1);
        unpack2(a1B, v0, v1);
        unpack2(a2B, w0, w1);
        const float inv2 = 1.0f / (sA + sB);
        outS[t + NTHR][0] = (u0 + u1) * inv2 + wp[24];
        outS[t + NTHR][1] = (v0 + v1) * inv2 + wp[25];
        outS[t + NTHR][2] = (w0 + w1) * inv2 + wp[26];
    }
    __syncthreads();

    // ---- losses (full patch: 960 elements) ----
    float lm = 0.f, la = 0.f, lr = 0.f;

    // all_loss / mid_loss: 960 elements (n,c,ph,pw), 6 per thread
#pragma unroll
    for (int i = 0; i < 6; i++) {
        const int e   = t + i * NTHR;
        const int n2  = e / 192;
        const int rem = e - n2 * 192;
        const int c   = rem >> 6;
        const int pp2 = rem & 63;
        const int h2  = r1 * IP + (pp2 >> 3);
        const int w2  = r2 * IP + (pp2 & 7);
        const float nin  = outp[((n2 * 3 + c) * HH + h2) * HH + w2];
        const float ninm = outp[((MID * 3 + c) * HH + h2) * HH + w2];
        const float al   = outS[n2 * 64 + pp2][c];
        const float da = nin - al;
        const float dm = ninm - al;
        la += da * da;
        lm += dm * dm;
    }

    // rec (mean over N) + rec_image write + rec_loss partial: 192 elements
    float* __restrict__ rec_out = out + 1;
#pragma unroll
    for (int i = 0; i < 2; i++) {
        const int e = t + i * NTHR;
        if (e < 192) {
            const int c   = e >> 6;
            const int pp2 = e & 63;
            const int h2  = r1 * IP + (pp2 >> 3);
            const int w2  = r2 * IP + (pp2 & 7);
            const float rec = 0.2f * (outS[pp2][c] + outS[64 + pp2][c] + outS[128 + pp2][c]
                                      + outS[192 + pp2][c] + outS[256 + pp2][c]);
            rec_out[(c * HH + h2) * HH + w2] = rec;
            const float om = outp[((MID * 3 + c) * HH + h2) * HH + w2];
            const float d  = om - rec;
            lr += d * d;
        }
    }

    // warp reduce then block reduce
#pragma unroll
    for (int o = 16; o > 0; o >>= 1) {
        lm += __shfl_down_sync(0xffffffffu, lm, o);
        la += __shfl_down_sync(0xffffffffu, la, o);
        lr += __shfl_down_sync(0xffffffffu, lr, o);
    }
    if ((t & 31) == 0) {
        atomicAdd(&red[0], lm);
        atomicAdd(&red[1], la);
        atomicAdd(&red[2], lr);
    }
    __syncthreads();

    if (t == 0) {
        atomicAdd(&g_mid_acc, red[0] * (1.0f / 960.0f));
        atomicAdd(&g_all_acc, red[1] * (1.0f / 960.0f));
        atomicAdd(&g_rec_acc, red[2]);
        __threadfence();
        const unsigned old = atomicAdd(&g_done, 1u);
        if (old == NBLK - 1) {
            // Last CTA: all accumulators visible. Finalize the loss.
            const float mid = atomicAdd(&g_mid_acc, 0.0f);
            const float all = atomicAdd(&g_all_acc, 0.0f);
            const float rcc = atomicAdd(&g_rec_acc, 0.0f);
            const float frac = 1.0f - (float)step[0] / (float)max_steps[0];
            const float f2 = frac * frac;
            const float f4 = f2 * f2;
            const float f8 = f4 * f4;
            const float coeff = loss_diff[0] * (f8 * f2);   // frac^10
            out[0] = mid + coeff * all + rcc * (1.0f / 196608.0f);
            // Reset globals for the next graph replay (zero-init covers call 1).
            g_mid_acc = 0.0f;
            g_all_acc = 0.0f;
            g_rec_acc = 0.0f;
            __threadfence();
            g_done = 0u;
        }
    }
}

extern "C" void kernel_launch(void* const* d_in, const int* in_sizes, int n_in,
                              void* d_out, int out_size)
{
    const float* inp  = (const float*)d_in[0];
    const float* outp = (const float*)d_in[1];
    const float* Wq   = (const float*)d_in[2];
    const float* Wk   = (const float*)d_in[3];
    const float* bq   = (const float*)d_in[4];
    const float* bk   = (const float*)d_in[5];
    const float* bv   = (const float*)d_in[6];
    const float* ld   = (const float*)d_in[7];
    const int*   st   = (const int*)d_in[8];
    const int*   ms   = (const int*)d_in[9];
    float* out = (float*)d_out;

    attn_loss_kernel<<<NBLK, NTHR>>>(inp, outp, Wq, Wk, bq, bk, bv, ld, st, ms, out);
}